// round 5
// baseline (speedup 1.0000x reference)
#include <cuda_runtime.h>
#include <math.h>
#include <float.h>

#define NN 8192
#define NE 65536
#define VPLANE ((size_t)NN * 576)

#define INV_SQRT128 0.08838834764831843f
#define INV_SQRT512 0.04419417382415922f
#define INV_SQRT3   0.5773502691896258f
#define INV_SQRT160 0.07905694150420949f
#define INV_SQRT32  0.17677669529663687f

#define SC_S   (0.125f * INV_SQRT128 * INV_SQRT160)
#define SC_V   (INV_SQRT32 * 0.125f * INV_SQRT160)
#define SC_P_S (INV_SQRT128)
#define SC_P_V (0.125f)
#define SC_C_S (0.125f * INV_SQRT512)
#define SC_C_V (0.125f * 0.0625f)

typedef unsigned long long u64;

__device__ __forceinline__ void fma2(u64& d, u64 a, u64 b) {
    asm("fma.rn.f32x2 %0, %1, %2, %0;" : "+l"(d) : "l"(a), "l"(b));
}
__device__ __forceinline__ u64 dupf(float x) {
    u64 r; asm("mov.b64 %0, {%1, %1};" : "=l"(r) : "r"(__float_as_uint(x))); return r;
}

// ---------------- scratch ------------------------------------------------------
__device__ float g_xT[160 * NN];
__device__ float g_S[NN * 1088];          // tk_s 512 | tself_s 512 | PA_s 32 | PB_s 32
__device__ float g_V[3 * NN * 576];       // plane c: tk_v 256 | tself_v 256 | PAv 32 | PBv 32
__device__ float g_QKself[NN * 8];
__device__ float g_logit[NE * 8];         // fallback (deg > 64)
__device__ float g_agg[NN * 1280];
__device__ float g_ms[NN * 64];
__device__ float g_mv[3 * NN * 32];
__device__ int   g_cnt[NN];
__device__ int   g_offs[NN + 1];
__device__ int   g_cursor[NN];
__device__ int   g_elist[NE];
__device__ float g_Wts[64 * 1088];
__device__ float g_Wtv[32 * 576];
__device__ float g_Wcs[512 * 64];
__device__ float g_Wcv[256 * 32];

// ---------------- weight packing / grams / hist -----------------------------------
__global__ void __launch_bounds__(256) k_pack2(
        const float* __restrict__ Wq_s, const float* __restrict__ Wq_v,
        const float* __restrict__ Wk_s, const float* __restrict__ Wk_v,
        const float* __restrict__ Wp_s, const float* __restrict__ Wp_v,
        const float* __restrict__ Wv_s, const float* __restrict__ Wv_v,
        const float* __restrict__ Wm_s, const float* __restrict__ Wm_v,
        const int* __restrict__ ei) {
    __shared__ float sm[8192];
    int b = blockIdx.x, tid = threadIdx.x;
    if (b >= 49) {                          // histogram over dst
        int e = (b - 49) * 256 + tid;
        if (e < NE) atomicAdd(&g_cnt[ei[NE + e]], 1);
        return;
    }
    if (b < 16) {
        int h = b & 7, self = b >> 3;
        float* Q = sm; float* Kx = sm + 4096;
        for (int i = tid; i < 4096; i += 256) {
            int a = i >> 6, j = i & 63;
            Q[i]  = Wq_s[a * 512 + h * 64 + j];
            int kr = self ? a : (64 + a);
            Kx[i] = Wk_s[kr * 512 + h * 64 + j];
        }
        __syncthreads();
        for (int i = tid; i < 4096; i += 256) {
            int a = i & 63, bb = i >> 6;
            float s = 0.f;
            for (int j = 0; j < 64; j++) s += Q[a * 64 + j] * Kx[bb * 64 + j];
            g_Wts[bb * 1088 + self * 512 + h * 64 + a] = s * SC_S;
        }
    } else if (b < 32) {
        int h = (b - 16) & 7, self = (b - 16) >> 3;
        float* Q = sm; float* Kx = sm + 1024;
        for (int i = tid; i < 1024; i += 256) {
            int a = i >> 5, j = i & 31;
            Q[i]  = Wq_v[a * 256 + h * 32 + j];
            int kr = self ? a : (32 + a);
            Kx[i] = Wk_v[kr * 256 + h * 32 + j];
        }
        __syncthreads();
        for (int i = tid; i < 1024; i += 256) {
            int a = i & 31, bb = i >> 5;
            float s = 0.f;
            for (int j = 0; j < 32; j++) s += Q[a * 32 + j] * Kx[bb * 32 + j];
            g_Wtv[bb * 576 + self * 256 + h * 32 + a] = s * SC_V;
        }
    } else if (b < 40) {
        int h = b - 32;
        float* V = sm; float* M = sm + 4096;
        for (int i = tid; i < 4096; i += 256) {
            int k = i >> 6, j = i & 63;
            V[i] = Wv_s[k * 512 + h * 64 + j];
            M[i] = Wm_s[(h * 64 + k) * 64 + j];
        }
        __syncthreads();
        for (int i = tid; i < 4096; i += 256) {
            int d = i & 63, k = i >> 6;
            float s = 0.f;
            for (int j = 0; j < 64; j++) s += V[k * 64 + j] * M[j * 64 + d];
            g_Wcs[(h * 64 + k) * 64 + d] = s * SC_C_S;
        }
    } else if (b < 48) {
        int h = b - 40;
        float* V = sm; float* M = sm + 1024;
        for (int i = tid; i < 1024; i += 256) {
            int k = i >> 5, j = i & 31;
            V[i] = Wv_v[k * 256 + h * 32 + j] + Wv_v[(32 + k) * 256 + h * 32 + j];
            M[i] = Wm_v[(h * 32 + k) * 32 + j];
        }
        __syncthreads();
        for (int i = tid; i < 1024; i += 256) {
            int d = i & 31, k = i >> 5;
            float s = 0.f;
            for (int j = 0; j < 32; j++) s += V[k * 32 + j] * M[j * 32 + d];
            g_Wcv[(h * 32 + k) * 32 + d] = s * SC_C_V;
        }
    } else {   // b == 48: Wp copies
        for (int i = tid; i < 4096; i += 256) {
            int bb = i >> 6, c = i & 63;
            float w = (c < 32) ? Wp_s[bb * 32 + c] : Wp_s[(64 + bb) * 32 + (c - 32)];
            g_Wts[bb * 1088 + 1024 + c] = w * SC_P_S;
        }
        for (int i = tid; i < 2048; i += 256) {
            int bb = i >> 6, c = i & 63;
            float w = (c < 32) ? Wp_v[bb * 32 + c] : Wp_v[(32 + bb) * 32 + (c - 32)];
            g_Wtv[bb * 576 + 512 + c] = w * SC_P_V;
        }
    }
}

// ---------------- transpose x -> xT [160][8192] ----------------------------------
__global__ void k_xT(const float* __restrict__ x, float* __restrict__ xT) {
    __shared__ float t[32][33];
    int tx = threadIdx.x, ty = threadIdx.y;
    int n0 = blockIdx.x * 32, t0 = blockIdx.y * 32;
#pragma unroll
    for (int i = 0; i < 32; i += 8)
        t[ty + i][tx] = x[(size_t)(n0 + ty + i) * 160 + t0 + tx];
    __syncthreads();
#pragma unroll
    for (int i = 0; i < 32; i += 8)
        xT[(size_t)(t0 + ty + i) * 8192 + n0 + tx] = t[tx][ty + i];
}

// ---------------- full-K resident GEMM, B pre-duplicated ---------------------------
// BM=64, BN=64. A row = baseRow + z + k*rowStride (rows of xT).
template<int K>
__global__ void __launch_bounds__(256) k_gemmT(
        const float* __restrict__ AT, int baseRow, int rowStride,
        const float* __restrict__ W, int N,
        float* __restrict__ C, int cRow, size_t planeStride) {
    __shared__ __align__(16) float As[K * 64];
    __shared__ __align__(16) u64 Ws2[K * 64];
    int tid = threadIdx.x;
    int n0 = blockIdx.x * 64, m0 = blockIdx.y * 64;
    int z = blockIdx.z;
#pragma unroll
    for (int r = 0; r < K / 16; r++) {
        int idx = tid + r * 256;
        int k = idx >> 4, mq = idx & 15;
        *(float4*)&As[k * 64 + mq * 4] =
            *(const float4*)&AT[(size_t)(baseRow + z + k * rowStride) * 8192 + m0 + mq * 4];
    }
#pragma unroll
    for (int r = 0; r < K / 16; r++) {
        int idx = tid + r * 256;
        int k = idx >> 4, j = idx & 15;
        float4 w = *(const float4*)&W[(size_t)k * N + n0 + j * 4];
        Ws2[k * 64 + j * 4 + 0] = dupf(w.x);
        Ws2[k * 64 + j * 4 + 1] = dupf(w.y);
        Ws2[k * 64 + j * 4 + 2] = dupf(w.z);
        Ws2[k * 64 + j * 4 + 3] = dupf(w.w);
    }
    __syncthreads();
    int ty = tid >> 4, tx = tid & 15;
    u64 acc[2][4] = {};
#pragma unroll 8
    for (int k = 0; k < K; k++) {
        ulonglong2 a = *(const ulonglong2*)&As[k * 64 + ty * 4];
        ulonglong2 b01 = *(const ulonglong2*)&Ws2[k * 64 + tx * 4];
        ulonglong2 b23 = *(const ulonglong2*)&Ws2[k * 64 + tx * 4 + 2];
        u64 bb[4] = {b01.x, b01.y, b23.x, b23.y};
#pragma unroll
        for (int j = 0; j < 4; j++) {
            fma2(acc[0][j], a.x, bb[j]);
            fma2(acc[1][j], a.y, bb[j]);
        }
    }
    float* Cb = C + (size_t)z * planeStride;
#pragma unroll
    for (int q = 0; q < 2; q++) {
        float2 c0 = *(float2*)&acc[q][0];
        float2 c1 = *(float2*)&acc[q][1];
        float2 c2 = *(float2*)&acc[q][2];
        float2 c3 = *(float2*)&acc[q][3];
        int r0 = m0 + ty * 4 + 2 * q;
        *(float4*)&Cb[(size_t)r0 * cRow + n0 + tx * 4]       = make_float4(c0.x, c1.x, c2.x, c3.x);
        *(float4*)&Cb[(size_t)(r0 + 1) * cRow + n0 + tx * 4] = make_float4(c0.y, c1.y, c2.y, c3.y);
    }
}

// ---------------- final projection: agg @ Wc -> g_ms / g_mv -------------------------
__global__ void __launch_bounds__(256) k_proj() {
    __shared__ __align__(16) char smraw[16384 + 16384];
    float* As = (float*)smraw;                 // [32][128]
    u64* Ws2 = (u64*)(smraw + 16384);          // [32][<=64]
    int tid = threadIdx.x;
    int b = blockIdx.x;
    if (b < 64) {       // scalar: [8192,512] @ [512,64]
        int m0 = b * 128;
        int ty = tid >> 4, tx = tid & 15;
        u64 acc[4][4] = {};
        for (int k0 = 0; k0 < 512; k0 += 32) {
            __syncthreads();
#pragma unroll
            for (int r = 0; r < 4; r++) {
                int idx = tid + r * 256;
                int m = idx & 127, kq = idx >> 7;
                float4 v = *(const float4*)&g_agg[(size_t)(m0 + m) * 1280 + k0 + kq * 4];
                As[(kq * 4 + 0) * 128 + m] = v.x;
                As[(kq * 4 + 1) * 128 + m] = v.y;
                As[(kq * 4 + 2) * 128 + m] = v.z;
                As[(kq * 4 + 3) * 128 + m] = v.w;
            }
#pragma unroll
            for (int r = 0; r < 2; r++) {
                int idx = tid + r * 256;
                int k = idx >> 4, j = idx & 15;
                float4 w = *(const float4*)&g_Wcs[(size_t)(k0 + k) * 64 + j * 4];
                Ws2[k * 64 + j * 4 + 0] = dupf(w.x);
                Ws2[k * 64 + j * 4 + 1] = dupf(w.y);
                Ws2[k * 64 + j * 4 + 2] = dupf(w.z);
                Ws2[k * 64 + j * 4 + 3] = dupf(w.w);
            }
            __syncthreads();
#pragma unroll 4
            for (int k = 0; k < 32; k++) {
                ulonglong2 a01 = *(const ulonglong2*)&As[k * 128 + ty * 8];
                ulonglong2 a23 = *(const ulonglong2*)&As[k * 128 + ty * 8 + 4];
                ulonglong2 b01 = *(const ulonglong2*)&Ws2[k * 64 + tx * 4];
                ulonglong2 b23 = *(const ulonglong2*)&Ws2[k * 64 + tx * 4 + 2];
                u64 ap[4] = {a01.x, a01.y, a23.x, a23.y};
                u64 bb[4] = {b01.x, b01.y, b23.x, b23.y};
#pragma unroll
                for (int q = 0; q < 4; q++)
#pragma unroll
                    for (int j = 0; j < 4; j++)
                        fma2(acc[q][j], ap[q], bb[j]);
            }
        }
#pragma unroll
        for (int q = 0; q < 4; q++) {
            float2 c0 = *(float2*)&acc[q][0];
            float2 c1 = *(float2*)&acc[q][1];
            float2 c2 = *(float2*)&acc[q][2];
            float2 c3 = *(float2*)&acc[q][3];
            int r0 = m0 + ty * 8 + 2 * q;
            *(float4*)&g_ms[(size_t)r0 * 64 + tx * 4]       = make_float4(c0.x, c1.x, c2.x, c3.x);
            *(float4*)&g_ms[(size_t)(r0 + 1) * 64 + tx * 4] = make_float4(c0.y, c1.y, c2.y, c3.y);
        }
    } else {            // vector: 3 x [8192,256] @ [256,32]
        int idx2 = b - 64;
        int c = idx2 / 64, mt = idx2 % 64;
        int m0 = mt * 128;
        int ty = tid >> 3, tx = tid & 7;
        u64 acc[2][4] = {};
        for (int k0 = 0; k0 < 256; k0 += 32) {
            __syncthreads();
#pragma unroll
            for (int r = 0; r < 4; r++) {
                int idx = tid + r * 256;
                int m = idx & 127, kq = idx >> 7;
                float4 v = *(const float4*)&g_agg[(size_t)(m0 + m) * 1280 + 512 + c * 256 + k0 + kq * 4];
                As[(kq * 4 + 0) * 128 + m] = v.x;
                As[(kq * 4 + 1) * 128 + m] = v.y;
                As[(kq * 4 + 2) * 128 + m] = v.z;
                As[(kq * 4 + 3) * 128 + m] = v.w;
            }
            {
                int k = tid >> 3, j = tid & 7;
                float4 w = *(const float4*)&g_Wcv[(size_t)(k0 + k) * 32 + j * 4];
                Ws2[k * 32 + j * 4 + 0] = dupf(w.x);
                Ws2[k * 32 + j * 4 + 1] = dupf(w.y);
                Ws2[k * 32 + j * 4 + 2] = dupf(w.z);
                Ws2[k * 32 + j * 4 + 3] = dupf(w.w);
            }
            __syncthreads();
#pragma unroll 4
            for (int k = 0; k < 32; k++) {
                ulonglong2 a = *(const ulonglong2*)&As[k * 128 + ty * 4];
                ulonglong2 b01 = *(const ulonglong2*)&Ws2[k * 32 + tx * 4];
                ulonglong2 b23 = *(const ulonglong2*)&Ws2[k * 32 + tx * 4 + 2];
                u64 bb[4] = {b01.x, b01.y, b23.x, b23.y};
#pragma unroll
                for (int j = 0; j < 4; j++) {
                    fma2(acc[0][j], a.x, bb[j]);
                    fma2(acc[1][j], a.y, bb[j]);
                }
            }
        }
        float* Cb = g_mv + (size_t)c * NN * 32;
#pragma unroll
        for (int q = 0; q < 2; q++) {
            float2 c0 = *(float2*)&acc[q][0];
            float2 c1 = *(float2*)&acc[q][1];
            float2 c2 = *(float2*)&acc[q][2];
            float2 c3 = *(float2*)&acc[q][3];
            int r0 = m0 + ty * 4 + 2 * q;
            *(float4*)&Cb[(size_t)r0 * 32 + tx * 4]       = make_float4(c0.x, c1.x, c2.x, c3.x);
            *(float4*)&Cb[(size_t)(r0 + 1) * 32 + tx * 4] = make_float4(c0.y, c1.y, c2.y, c3.y);
        }
    }
}

// ---------------- self term: warp per node ----------------------------------------
__global__ void __launch_bounds__(256) k_qkself2(const float* __restrict__ x) {
    __shared__ float s_x[8][160];
    int tid = threadIdx.x;
    int wid = tid >> 5, lane = tid & 31;
    int n = blockIdx.x * 8 + wid;
    const float4* xs = (const float4*)(x + (size_t)n * 160);
    ((float4*)s_x[wid])[lane] = xs[lane];
    if (lane < 8) ((float4*)s_x[wid])[32 + lane] = xs[32 + lane];
    __syncwarp();
    const float* xr = s_x[wid];
    const float* Sb = g_S + (size_t)n * 1088 + 512;
#pragma unroll
    for (int h = 0; h < 8; h++) {
        float a = Sb[h * 64 + lane] * xr[lane]
                + Sb[h * 64 + 32 + lane] * xr[32 + lane];
#pragma unroll
        for (int c = 0; c < 3; c++)
            a += g_V[c * VPLANE + (size_t)n * 576 + 256 + h * 32 + lane]
                 * xr[64 + lane * 3 + c];
#pragma unroll
        for (int o = 16; o; o >>= 1) a += __shfl_xor_sync(0xffffffffu, a, o);
        if (lane == 0) g_QKself[n * 8 + h] = a;
    }
}

// ---------------- CSR --------------------------------------------------------------
__global__ void __launch_bounds__(1024) k_scan() {
    __shared__ int wsum[32];
    int tid = threadIdx.x;
    int base = tid * 8;
    int loc[8]; int tot = 0;
#pragma unroll
    for (int i = 0; i < 8; i++) { loc[i] = tot; tot += g_cnt[base + i]; }
    int lane = tid & 31, w = tid >> 5;
    int incl = tot;
#pragma unroll
    for (int o = 1; o < 32; o <<= 1) {
        int y = __shfl_up_sync(0xffffffffu, incl, o);
        if (lane >= o) incl += y;
    }
    if (lane == 31) wsum[w] = incl;
    int excl = incl - tot;
    __syncthreads();
    if (w == 0) {
        int t = wsum[lane];
        int i2 = t;
#pragma unroll
        for (int o = 1; o < 32; o <<= 1) {
            int y = __shfl_up_sync(0xffffffffu, i2, o);
            if (lane >= o) i2 += y;
        }
        wsum[lane] = i2 - t;
    }
    __syncthreads();
    int off = wsum[w] + excl;
#pragma unroll
    for (int i = 0; i < 8; i++) {
        int o2 = off + loc[i];
        g_offs[base + i] = o2;
        g_cursor[base + i] = o2;
    }
    if (tid == 1023) g_offs[NN] = NE;
}

__global__ void k_scatter(const int* __restrict__ ei) {
    int e = blockIdx.x * 256 + threadIdx.x;
    if (e < NE) {
        int pos = atomicAdd(&g_cursor[ei[NE + e]], 1);
        g_elist[pos] = e;
    }
}

// ---------------- fused attention + feat + aggregation: warp per node ----------------
__global__ void __launch_bounds__(256) k_attn_agg3(const float* __restrict__ x,
                                                   const int* __restrict__ ei,
                                                   const float* __restrict__ rbf,
                                                   const float* __restrict__ rsh,
                                                   const float* __restrict__ Wrbf) {
    __shared__ float s_x[8][160];
    __shared__ float s_lg[8][512];
    __shared__ float sW[1024];
    const unsigned F = 0xffffffffu;
    int tid = threadIdx.x;
    int wid = tid >> 5, lane = tid & 31;
    int n = blockIdx.x * 8 + wid;
    int h = lane >> 2, p = lane & 3;

    for (int l = tid; l < 1024; l += 256) sW[l] = Wrbf[l];
    __syncthreads();

    int s0 = g_offs[n], deg = g_offs[n + 1] - s0;
    float* lg = (deg <= 64) ? &s_lg[wid][0] : (g_logit + (size_t)s0 * 8);

    int e0 = 0, e1 = 0, src0 = 0, src1 = 0;
    if (lane < deg) e0 = g_elist[s0 + lane];
    if (lane + 32 < deg) e1 = g_elist[s0 + 32 + lane];
    if (lane < deg) src0 = ei[e0];
    if (lane + 32 < deg) src1 = ei[e1];

    float mymax = -FLT_MAX;
    {
        float tk[40];
#pragma unroll
        for (int tt = 0; tt < 40; tt++) {
            int t = p * 40 + tt;
            if (t < 64)
                tk[tt] = g_S[(size_t)n * 1088 + h * 64 + t];
            else {
                int j = t - 64;
                tk[tt] = g_V[(j % 3) * VPLANE + (size_t)n * 576 + h * 32 + (j / 3)];
            }
        }
        for (int i = 0; i < deg; i++) {
            int e, src;
            if (i < 64) {
                e   = __shfl_sync(F, (i < 32) ? e0 : e1, i & 31);
                src = __shfl_sync(F, (i < 32) ? src0 : src1, i & 31);
            } else {
                int ee = 0, ss = 0;
                if (lane == 0) { ee = g_elist[s0 + i]; ss = ei[ee]; }
                e = __shfl_sync(F, ee, 0);
                src = __shfl_sync(F, ss, 0);
            }
            const float4* xs = (const float4*)(x + (size_t)src * 160);
            ((float4*)s_x[wid])[lane] = xs[lane];
            if (lane < 8) ((float4*)s_x[wid])[32 + lane] = xs[32 + lane];
            __syncwarp();
            const float* xr = s_x[wid] + p * 40;
            float a = 0.f;
#pragma unroll
            for (int tt = 0; tt < 40; tt++) a += tk[tt] * xr[tt];
            a += __shfl_xor_sync(F, a, 1);
            a += __shfl_xor_sync(F, a, 2);
            if (p == 0) {
                a += g_QKself[src * 8 + h];
                lg[i * 8 + h] = a;
                mymax = fmaxf(mymax, a);
            }
            __syncwarp();
        }
    }

    if (p == 0 && deg > 0) {
        float den = 0.f;
        for (int i = 0; i < deg; i++) {
            float ex = expf(lg[i * 8 + h] - mymax);
            lg[i * 8 + h] = ex;
            den += ex;
        }
        float inv = 1.f / den;
        for (int i = 0; i < deg; i++) lg[i * 8 + h] *= inv;
    }
    __syncwarp();

    // dst-side filter terms (constant per warp)
    float pbs = g_S[(size_t)n * 1088 + 1056 + lane];
    float pbv[3];
#pragma unroll
    for (int c = 0; c < 3; c++)
        pbv[c] = g_V[c * VPLANE + (size_t)n * 576 + 544 + lane];

    float acc[40];
#pragma unroll
    for (int tt = 0; tt < 40; tt++) acc[tt] = 0.f;

    for (int i = 0; i < deg; i++) {
        int e, src;
        if (i < 64) {
            e   = __shfl_sync(F, (i < 32) ? e0 : e1, i & 31);
            src = __shfl_sync(F, (i < 32) ? src0 : src1, i & 31);
        } else {
            int ee = 0, ss = 0;
            if (lane == 0) { ee = g_elist[s0 + i]; ss = ei[ee]; }
            e = __shfl_sync(F, ee, 0);
            src = __shfl_sync(F, ss, 0);
        }
        // inline feat computation (lane = irrep index d)
        float rval = (lane < 16) ? rbf[e * 16 + lane] : 0.f;
        float scal_s = 0.f, scal_v = 0.f;
#pragma unroll
        for (int bq = 0; bq < 16; bq++) {
            float rb = __shfl_sync(F, rval, bq);
            scal_s += rb * sW[bq * 64 + lane];
            scal_v += rb * sW[bq * 64 + 32 + lane];
        }
        float ps = g_S[(size_t)src * 1088 + 1024 + lane] + pbs;
        float sph = rsh[e * 128 + lane] * scal_s * ps;
        float sv[3];
#pragma unroll
        for (int c = 0; c < 3; c++) {
            float pv = g_V[c * VPLANE + (size_t)src * 576 + 512 + lane] + pbv[c];
            sv[c] = rsh[e * 128 + 32 + lane * 3 + c] * scal_v * pv;
        }
        float f0 = sph * sph;
        float f1 = (sv[0] * sv[0] + sv[1] * sv[1] + sv[2] * sv[2]) * INV_SQRT3;
        float fv0 = sph * sv[0], fv1 = sph * sv[1], fv2 = sph * sv[2];

        float at[8];
#pragma unroll
        for (int hh = 0; hh < 8; hh++) at[hh] = lg[i * 8 + hh];
#pragma unroll
        for (int tt = 0; tt < 40; tt++) {
            int hT = (tt < 16) ? (tt >> 1) : ((tt - 16) & 7);
            float fval;
            if (tt < 16) fval = (tt & 1) ? f1 : f0;
            else {
                int c = (tt - 16) >> 3;
                fval = (c == 0) ? fv0 : ((c == 1) ? fv1 : fv2);
            }
            acc[tt] += at[hT] * fval;
        }
    }
#pragma unroll
    for (int tt = 0; tt < 40; tt++)
        g_agg[(size_t)n * 1280 + tt * 32 + lane] = acc[tt];
}

// ---------------- NormGate + output --------------------------------------------------
__global__ void __launch_bounds__(256) k_normgate(const float* __restrict__ ln_g,
                                                  const float* __restrict__ ln_b,
                                                  const float* __restrict__ W1,
                                                  const float* __restrict__ b1,
                                                  const float* __restrict__ W2,
                                                  const float* __restrict__ b2,
                                                  float* __restrict__ out) {
    __shared__ float sW1[96 * 96];
    __shared__ float sX[8][96];
    __shared__ float sH[8][96];
    int tid = threadIdx.x;
    int w = tid >> 5, lane = tid & 31;
    for (int i = tid; i < 9216; i += 256) sW1[i] = W1[i];
    __syncthreads();

    for (int sub = 0; sub < 4; sub++) {
        int n = blockIdx.x * 32 + w * 4 + sub;
        float ms0 = g_ms[(size_t)n * 64 + lane];
        float ms1 = g_ms[(size_t)n * 64 + 32 + lane];
        float v0 = g_mv[(size_t)0 * NN * 32 + n * 32 + lane];
        float v1 = g_mv[(size_t)1 * NN * 32 + n * 32 + lane];
        float v2 = g_mv[(size_t)2 * NN * 32 + n * 32 + lane];
        float n00 = fabsf(ms0), n01 = fabsf(ms1);
        float n02 = sqrtf(v0 * v0 + v1 * v1 + v2 * v2);
        float s = n00 + n01 + n02;
        float s2 = n00 * n00 + n01 * n01 + n02 * n02;
#pragma unroll
        for (int o = 16; o; o >>= 1) {
            s  += __shfl_xor_sync(0xffffffffu, s, o);
            s2 += __shfl_xor_sync(0xffffffffu, s2, o);
        }
        float mu = s * (1.f / 96.f);
        float var = s2 * (1.f / 96.f) - mu * mu;
        float rstd = rsqrtf(var + 1e-5f);
        sX[w][lane]      = (n00 - mu) * rstd * ln_g[lane]      + ln_b[lane];
        sX[w][lane + 32] = (n01 - mu) * rstd * ln_g[lane + 32] + ln_b[lane + 32];
        sX[w][lane + 64] = (n02 - mu) * rstd * ln_g[lane + 64] + ln_b[lane + 64];
        __syncwarp();
#pragma unroll
        for (int t = 0; t < 3; t++) {
            int jp = lane + t * 32;
            float hs = b1[jp];
            for (int j = 0; j < 96; j++) hs += sX[w][j] * sW1[j * 96 + jp];
            sH[w][jp] = hs / (1.f + expf(-hs));
        }
        __syncwarp();
        float n0arr[3] = {n00, n01, n02};
        float f[3];
#pragma unroll
        for (int t = 0; t < 3; t++) {
            int jp = lane + t * 32;
            float gs = b2[jp];
            for (int j = 0; j < 96; j++) gs += sH[w][j] * W2[j * 96 + jp];
            float gg = gs / (1.f + expf(-gs));
            f[t] = gg / (n0arr[t] + 1e-6f);
        }
        out[n * 160 + lane]      = ms0 * f[0];
        out[n * 160 + 32 + lane] = ms1 * f[1];
        out[n * 160 + 64 + lane * 3 + 0] = v0 * f[2];
        out[n * 160 + 64 + lane * 3 + 1] = v1 * f[2];
        out[n * 160 + 64 + lane * 3 + 2] = v2 * f[2];
        __syncwarp();
    }
}

// ---------------- launch ----------------------------------------------------------------
extern "C" void kernel_launch(void* const* d_in, const int* in_sizes, int n_in,
                              void* d_out, int out_size) {
    const float* pseduo_x = (const float*)d_in[0];
    const float* rbf   = (const float*)d_in[1];
    const float* rsh   = (const float*)d_in[2];
    const int*   ei    = (const int*)d_in[3];
    const float* Wq_s  = (const float*)d_in[4];
    const float* Wq_v  = (const float*)d_in[5];
    const float* Wk_s  = (const float*)d_in[6];
    const float* Wk_v  = (const float*)d_in[7];
    const float* Wp_s  = (const float*)d_in[8];
    const float* Wp_v  = (const float*)d_in[9];
    const float* Wrbf  = (const float*)d_in[10];
    const float* Wv_s  = (const float*)d_in[11];
    const float* Wv_v  = (const float*)d_in[12];
    const float* Wm_s  = (const float*)d_in[13];
    const float* Wm_v  = (const float*)d_in[14];
    const float* ln_g  = (const float*)d_in[15];
    const float* ln_b  = (const float*)d_in[16];
    const float* W1    = (const float*)d_in[17];
    const float* b1    = (const float*)d_in[18];
    const float* W2    = (const float*)d_in[19];
    const float* b2    = (const float*)d_in[20];
    float* out = (float*)d_out;

    void* p;
    cudaGetSymbolAddress(&p, g_xT);  float* XT  = (float*)p;
    cudaGetSymbolAddress(&p, g_S);   float* S   = (float*)p;
    cudaGetSymbolAddress(&p, g_V);   float* V   = (float*)p;
    cudaGetSymbolAddress(&p, g_cnt); int*   CNT = (int*)p;
    cudaGetSymbolAddress(&p, g_Wts); float* Wts = (float*)p;
    cudaGetSymbolAddress(&p, g_Wtv); float* Wtv = (float*)p;

    cudaMemsetAsync(CNT, 0, NN * sizeof(int));
    k_pack2<<<305, 256>>>(Wq_s, Wq_v, Wk_s, Wk_v, Wp_s, Wp_v, Wv_s, Wv_v, Wm_s, Wm_v, ei);
    k_xT<<<dim3(256, 5), dim3(32, 8)>>>(pseduo_x, XT);

    k_gemmT<64><<<dim3(17, 128, 1), 256>>>(XT, 0, 1, Wts, 1088, S, 1088, 0);
    k_gemmT<32><<<dim3(9, 128, 3), 256>>>(XT, 64, 3, Wtv, 576, V, 576, VPLANE);
    k_qkself2<<<1024, 256>>>(pseduo_x);

    k_scan<<<1, 1024>>>();
    k_scatter<<<256, 256>>>(ei);

    k_attn_agg3<<<1024, 256>>>(pseduo_x, ei, rbf, rsh, Wrbf);

    k_proj<<<256, 256>>>();
    k_normgate<<<256, 256>>>(ln_g, ln_b, W1, b1, W2, b2, out);
}